// round 16
// baseline (speedup 1.0000x reference)
#include <cuda_runtime.h>
#include <cuda_bf16.h>
#include <cuda_fp16.h>
#include <stdint.h>
#include <math.h>

#define B_   4
#define S_   1024
#define D_   2048
#define NH_  16
#define NKV_ 8
#define HD_  128
#define NREP_ 2
#define K_   8
#define FFN_ 5632
#define V_   32000
#define LAT_ 1024
#define HID_ 2048
#define EPS_ 1e-5f

typedef __nv_bfloat16 bf16;
typedef __half f16;

// ---------------- fp32 scratch ----------------
__device__ float g_h   [B_*S_*D_];
__device__ float g_v   [B_*S_*NKV_*HD_];
__device__ float g_sc  [(size_t)B_*NH_*S_*S_];
__device__ float g_f1  [B_*S_*FFN_];
__device__ float g_spec[B_*K_*D_];

// ---------------- activation scratch ----------------
__device__ f16  s_xf [B_*S_*D_];
__device__ f16  s_atf[B_*S_*D_];
__device__ f16  s_ff [B_*S_*FFN_];
__device__ bf16 s_qh [B_*S_*D_],        s_ql [B_*S_*D_];
__device__ bf16 s_kh [B_*S_*NKV_*HD_],  s_kl [B_*S_*NKV_*HD_];
__device__ bf16 s_vth[B_*NKV_*HD_*S_],  s_vtl[B_*NKV_*HD_*S_];
__device__ bf16 s_ph [(size_t)B_*NH_*S_*S_], s_pl [(size_t)B_*NH_*S_*S_];
__device__ bf16 s_h1h[B_*HID_],         s_h1l[B_*HID_];
__device__ bf16 s_sph[B_*LAT_],         s_spl[B_*LAT_];

// ---------------- transposed weights [N][K] ----------------
__device__ bf16 w_pw1h[HID_*LAT_],      w_pw1l[HID_*LAT_];
__device__ bf16 w_pw2h[K_*D_*HID_],     w_pw2l[K_*D_*HID_];
__device__ f16  w_qh [2*D_*D_],         w_ql [2*D_*D_];
__device__ f16  w_kh [2*NKV_*HD_*D_],   w_kl [2*NKV_*HD_*D_];
__device__ f16  w_vh [2*NKV_*HD_*D_],   w_vl [2*NKV_*HD_*D_];
__device__ f16  w_oh [2*D_*D_],         w_ol [2*D_*D_];
__device__ f16  w_1h [2*FFN_*D_],       w_1l [2*FFN_*D_];
__device__ f16  w_3h [2*FFN_*D_],       w_3l [2*FFN_*D_];
__device__ f16  w_2h [2*D_*FFN_],       w_2l [2*D_*FFN_];
__device__ f16  w_owh[(size_t)V_*D_],   w_owl[(size_t)V_*D_];

// ---------------- reductions ----------------
__device__ __forceinline__ float blockReduceSum(float v) {
    __shared__ float sh[32];
    __syncthreads();
    int lane = threadIdx.x & 31, wid = threadIdx.x >> 5;
    #pragma unroll
    for (int o = 16; o; o >>= 1) v += __shfl_down_sync(0xffffffffu, v, o);
    if (lane == 0) sh[wid] = v;
    __syncthreads();
    int nw = (blockDim.x + 31) >> 5;
    v = (threadIdx.x < nw) ? sh[threadIdx.x] : 0.f;
    if (wid == 0) {
        #pragma unroll
        for (int o = 16; o; o >>= 1) v += __shfl_down_sync(0xffffffffu, v, o);
        if (lane == 0) sh[0] = v;
    }
    __syncthreads();
    return sh[0];
}
__device__ __forceinline__ float blockReduceMax(float v) {
    __shared__ float sh[32];
    __syncthreads();
    int lane = threadIdx.x & 31, wid = threadIdx.x >> 5;
    #pragma unroll
    for (int o = 16; o; o >>= 1) v = fmaxf(v, __shfl_down_sync(0xffffffffu, v, o));
    if (lane == 0) sh[wid] = v;
    __syncthreads();
    int nw = (blockDim.x + 31) >> 5;
    v = (threadIdx.x < nw) ? sh[threadIdx.x] : -3.4e38f;
    if (wid == 0) {
        #pragma unroll
        for (int o = 16; o; o >>= 1) v = fmaxf(v, __shfl_down_sync(0xffffffffu, v, o));
        if (lane == 0) sh[0] = v;
    }
    __syncthreads();
    return sh[0];
}
__device__ __forceinline__ void split2(float v, bf16* hp, bf16* lp) {
    bf16 hi = __float2bfloat16(v);
    *hp = hi;
    *lp = __float2bfloat16(v - __bfloat162float(hi));
}
__device__ __forceinline__ unsigned pack2(float v0, float v1, unsigned &ulo) {
    bf16 h0 = __float2bfloat16(v0);
    bf16 l0 = __float2bfloat16(v0 - __bfloat162float(h0));
    bf16 h1 = __float2bfloat16(v1);
    bf16 l1 = __float2bfloat16(v1 - __bfloat162float(h1));
    ulo = (unsigned)__bfloat16_as_ushort(l0) | ((unsigned)__bfloat16_as_ushort(l1) << 16);
    return (unsigned)__bfloat16_as_ushort(h0) | ((unsigned)__bfloat16_as_ushort(h1) << 16);
}
__device__ __forceinline__ unsigned pack2f(float v0, float v1, unsigned &ulo) {
    f16 h0 = __float2half_rn(v0);
    f16 l0 = __float2half_rn(v0 - __half2float(h0));
    f16 h1 = __float2half_rn(v1);
    f16 l1 = __float2half_rn(v1 - __half2float(h1));
    ulo = (unsigned)__half_as_ushort(l0) | ((unsigned)__half_as_ushort(l1) << 16);
    return (unsigned)__half_as_ushort(h0) | ((unsigned)__half_as_ushort(h1) << 16);
}
__device__ __forceinline__ unsigned packh(float v0, float v1) {
    return (unsigned)__half_as_ushort(__float2half_rn(v0)) |
           ((unsigned)__half_as_ushort(__float2half_rn(v1)) << 16);
}

// ---------------- tiling constants ----------------
#define BM 128
#define BN 128
#define BK 32
#define LDS_ROW 40
#define TILE_H (BM * LDS_ROW)
#define STAGE_H (4 * TILE_H)
#define SMEM_BYTES (2 * STAGE_H * 2)        // bf16 3-term, 2-stage: 81920
#define STAGE_F_H (3 * TILE_H)
#define SMEM_F_BYTES (3 * STAGE_F_H * 2)    // fp16 2-term, 3-stage: 92160

#define MMA_BF16(d, a, b)                                                          \
    asm volatile("mma.sync.aligned.m16n8k16.row.col.f32.bf16.bf16.f32 "            \
                 "{%0,%1,%2,%3},{%4,%5,%6,%7},{%8,%9},{%0,%1,%2,%3};"              \
                 : "+f"(d[0]), "+f"(d[1]), "+f"(d[2]), "+f"(d[3])                  \
                 : "r"(a[0]), "r"(a[1]), "r"(a[2]), "r"(a[3]), "r"(b[0]), "r"(b[1]))

#define MMA_F16(d, a, b)                                                           \
    asm volatile("mma.sync.aligned.m16n8k16.row.col.f32.f16.f16.f32 "              \
                 "{%0,%1,%2,%3},{%4,%5,%6,%7},{%8,%9},{%0,%1,%2,%3};"              \
                 : "+f"(d[0]), "+f"(d[1]), "+f"(d[2]), "+f"(d[3])                  \
                 : "r"(a[0]), "r"(a[1]), "r"(a[2]), "r"(a[3]), "r"(b[0]), "r"(b[1]))

#define LDSM_X4(r0, r1, r2, r3, a)                                                 \
    asm volatile("ldmatrix.sync.aligned.m8n8.x4.shared.b16 {%0,%1,%2,%3}, [%4];"   \
                 : "=r"(r0), "=r"(r1), "=r"(r2), "=r"(r3) : "r"(a))

__device__ __forceinline__ void cpasync16(uint32_t dst, const void* src, int srcBytes) {
    asm volatile("cp.async.cg.shared.global [%0], [%1], 16, %2;"
                 :: "r"(dst), "l"(src), "r"(srcBytes));
}

// ================= GEMM (bf16 3-term, 2-stage) — attention / spectral path =================
__global__ void __launch_bounds__(256)
gemm_bf16_kernel(const bf16* __restrict__ Ah, const bf16* __restrict__ Al,
                 const bf16* __restrict__ Bh, const bf16* __restrict__ Bl,
                 float* __restrict__ C, bf16* __restrict__ Ch, bf16* __restrict__ Cl,
                 f16* __restrict__ Cf,
                 int M, int N, int Kd, int lda, int ldb, int ldc,
                 long long sA1, long long sA2, long long sB1, long long sB2,
                 long long sC1, long long sC2,
                 int nb2, int bDiv, float alpha, int accum,
                 int causalSkip, int causalK)
{
    int m0 = blockIdx.y * BM, n0 = blockIdx.x * BN;
    if (causalSkip && n0 >= m0 + BM) return;

    int z = blockIdx.z;
    int b1 = z / nb2, b2 = z % nb2;
    size_t offA = (size_t)b1 * sA1 + (size_t)b2 * sA2;
    size_t offB = (size_t)b1 * sB1 + (size_t)(b2 / bDiv) * sB2;
    size_t offC = (size_t)b1 * sC1 + (size_t)b2 * sC2;
    Ah += offA; Al += offA; Bh += offB; Bl += offB;

    int Klim = (causalK && m0 + BM < Kd) ? (m0 + BM) : Kd;
    int nk = Klim / BK;

    extern __shared__ bf16 smem[];
    uint32_t sbase = (uint32_t)__cvta_generic_to_shared(smem);

    int tid  = threadIdx.x;
    int lane = tid & 31;
    int warp = tid >> 5;
    int wm = warp >> 2, wn = warp & 3;

    int aRow = wm * 64 + (lane & 15);
    int aCol = (lane >> 4) << 3;
    int bRow = wn * 32 + ((lane >> 4) << 3) + (lane & 7);
    int bCol = (lane & 8);

    float c[4][4][4];
    #pragma unroll
    for (int i = 0; i < 4; i++)
        #pragma unroll
        for (int j = 0; j < 4; j++)
            #pragma unroll
            for (int t = 0; t < 4; t++) c[i][j][t] = 0.f;

    auto copyStage = [&](int kt) {
        uint32_t s0 = sbase + (uint32_t)(kt & 1) * STAGE_H * 2;
        int k0 = kt * BK;
        #pragma unroll
        for (int i = 0; i < 2; i++) {
            int cid = tid + i * 256;
            int row = cid >> 2, kc = (cid & 3) * 8;
            size_t go = (size_t)(m0 + row) * lda + k0 + kc;
            int pm = ((m0 + row) < M) ? 16 : 0;
            uint32_t da = s0 + (uint32_t)(row * LDS_ROW + kc) * 2;
            cpasync16(da,               Ah + go, pm);
            cpasync16(da + TILE_H * 2,  Al + go, pm);
            size_t gb = (size_t)(n0 + row) * ldb + k0 + kc;
            uint32_t db = s0 + (uint32_t)(2 * TILE_H + row * LDS_ROW + kc) * 2;
            cpasync16(db,               Bh + gb, 16);
            cpasync16(db + TILE_H * 2,  Bl + gb, 16);
        }
        asm volatile("cp.async.commit_group;");
    };

    copyStage(0);
    for (int kt = 0; kt < nk; kt++) {
        asm volatile("cp.async.wait_group 0;");
        __syncthreads();
        if (kt + 1 < nk) copyStage(kt + 1);

        uint32_t s0 = sbase + (uint32_t)(kt & 1) * STAGE_H * 2;

        #pragma unroll
        for (int s = 0; s < 2; s++) {
            int kc = s * 16;
            unsigned ah[4][4], al[4][4], bh[4][2], bl[4][2];
            #pragma unroll
            for (int mt = 0; mt < 4; mt++) {
                uint32_t adr = s0 + (uint32_t)((aRow + mt * 16) * LDS_ROW + kc + aCol) * 2;
                LDSM_X4(ah[mt][0], ah[mt][1], ah[mt][2], ah[mt][3], adr);
                LDSM_X4(al[mt][0], al[mt][1], al[mt][2], al[mt][3], adr + TILE_H * 2);
            }
            #pragma unroll
            for (int p = 0; p < 2; p++) {
                uint32_t adr = s0 + (uint32_t)(2 * TILE_H + (bRow + p * 16) * LDS_ROW + kc + bCol) * 2;
                unsigned r0, r1, r2, r3;
                LDSM_X4(r0, r1, r2, r3, adr);
                bh[2*p][0] = r0; bh[2*p][1] = r1; bh[2*p+1][0] = r2; bh[2*p+1][1] = r3;
                LDSM_X4(r0, r1, r2, r3, adr + TILE_H * 2);
                bl[2*p][0] = r0; bl[2*p][1] = r1; bl[2*p+1][0] = r2; bl[2*p+1][1] = r3;
            }
            #pragma unroll
            for (int mt = 0; mt < 4; mt++)
                #pragma unroll
                for (int nt = 0; nt < 4; nt++) {
                    MMA_BF16(c[mt][nt], ah[mt], bh[nt]);
                    MMA_BF16(c[mt][nt], ah[mt], bl[nt]);
                    MMA_BF16(c[mt][nt], al[mt], bh[nt]);
                }
        }
        __syncthreads();
    }

    #pragma unroll
    for (int mt = 0; mt < 4; mt++) {
        #pragma unroll
        for (int nt = 0; nt < 4; nt++) {
            int row = m0 + wm * 64 + mt * 16 + (lane >> 2);
            int col = n0 + wn * 32 + nt * 8 + (lane & 3) * 2;
            if (Cf || Ch) {
                #pragma unroll
                for (int pr = 0; pr < 2; pr++) {
                    int gm = row + pr * 8;
                    if (gm >= M) continue;
                    float v0 = c[mt][nt][pr * 2]     * alpha;
                    float v1 = c[mt][nt][pr * 2 + 1] * alpha;
                    size_t ci = offC + (size_t)gm * ldc + col;
                    if (Cf) {
                        *(unsigned*)(Cf + ci) = packh(v0, v1);
                    } else {
                        unsigned ulo;
                        unsigned uhi = pack2(v0, v1, ulo);
                        *(unsigned*)(Ch + ci) = uhi;
                        *(unsigned*)(Cl + ci) = ulo;
                    }
                }
            } else {
                #pragma unroll
                for (int t = 0; t < 4; t++) {
                    int gm = row + (t >> 1) * 8;
                    int gn = col + (t & 1);
                    if (gm >= M || gn >= N) continue;
                    float vv = c[mt][nt][t] * alpha;
                    size_t ci = offC + (size_t)gm * ldc + gn;
                    if (accum) vv += C[ci];
                    C[ci] = vv;
                }
            }
        }
    }
}

// ================= GEMM (fp16 2-term, BN=128, 3-stage, M-fastest grid) =================
// act: 0=none (fp32 C, optional accum), 2=silu-gate (C gate in, Cf f16 out),
//      3=rope (Ch/Cl bf16 pair out)
__global__ void __launch_bounds__(256)
gemm_f16_kernel(const f16* __restrict__ A,
                const f16* __restrict__ Bh, const f16* __restrict__ Bl,
                float* __restrict__ C, bf16* __restrict__ Ch, bf16* __restrict__ Cl,
                f16* __restrict__ Cf,
                int M, int N, int Kd, int lda, int ldb, int ldc,
                float alpha, int act, int accum)
{
    // M on blockIdx.x (fastest) so co-resident blocks share B tiles via L2.
    int m0 = blockIdx.x * BM, n0 = blockIdx.y * BN;
    int nk = Kd / BK;

    extern __shared__ f16 smemf[];
    uint32_t sbase = (uint32_t)__cvta_generic_to_shared(smemf);

    int tid  = threadIdx.x;
    int lane = tid & 31;
    int warp = tid >> 5;
    int wm = warp >> 2, wn = warp & 3;

    int aRow = wm * 64 + (lane & 15);
    int aCol = (lane >> 4) << 3;
    int bRow = wn * 32 + ((lane >> 4) << 3) + (lane & 7);
    int bCol = (lane & 8);

    float c[4][4][4];
    #pragma unroll
    for (int i = 0; i < 4; i++)
        #pragma unroll
        for (int j = 0; j < 4; j++)
            #pragma unroll
            for (int t = 0; t < 4; t++) c[i][j][t] = 0.f;

    auto copyStage = [&](int kt) {
        int st = kt % 3;
        uint32_t s0 = sbase + (uint32_t)st * STAGE_F_H * 2;
        int k0 = kt * BK;
        #pragma unroll
        for (int i = 0; i < 2; i++) {
            int cid = tid + i * 256;
            int row = cid >> 2, kc = (cid & 3) * 8;
            size_t go = (size_t)(m0 + row) * lda + k0 + kc;
            int pm = ((m0 + row) < M) ? 16 : 0;
            uint32_t da = s0 + (uint32_t)(row * LDS_ROW + kc) * 2;
            cpasync16(da, A + go, pm);
            size_t gb = (size_t)(n0 + row) * ldb + k0 + kc;
            uint32_t db = s0 + (uint32_t)(TILE_H + row * LDS_ROW + kc) * 2;
            cpasync16(db,              Bh + gb, 16);
            cpasync16(db + TILE_H * 2, Bl + gb, 16);
        }
        asm volatile("cp.async.commit_group;");
    };

    copyStage(0);
    if (nk > 1) copyStage(1);
    for (int kt = 0; kt < nk; kt++) {
        if (kt + 1 < nk) asm volatile("cp.async.wait_group 1;");
        else             asm volatile("cp.async.wait_group 0;");
        __syncthreads();
        if (kt + 2 < nk) copyStage(kt + 2);

        uint32_t s0 = sbase + (uint32_t)(kt % 3) * STAGE_F_H * 2;

        #pragma unroll
        for (int s = 0; s < 2; s++) {
            int kc = s * 16;
            unsigned a[4][4], bh[4][2], bl[4][2];
            #pragma unroll
            for (int mt = 0; mt < 4; mt++) {
                uint32_t adr = s0 + (uint32_t)((aRow + mt * 16) * LDS_ROW + kc + aCol) * 2;
                LDSM_X4(a[mt][0], a[mt][1], a[mt][2], a[mt][3], adr);
            }
            #pragma unroll
            for (int p = 0; p < 2; p++) {
                uint32_t adr = s0 + (uint32_t)(TILE_H + (bRow + p * 16) * LDS_ROW + kc + bCol) * 2;
                unsigned r0, r1, r2, r3;
                LDSM_X4(r0, r1, r2, r3, adr);
                bh[2*p][0] = r0; bh[2*p][1] = r1; bh[2*p+1][0] = r2; bh[2*p+1][1] = r3;
                LDSM_X4(r0, r1, r2, r3, adr + TILE_H * 2);
                bl[2*p][0] = r0; bl[2*p][1] = r1; bl[2*p+1][0] = r2; bl[2*p+1][1] = r3;
            }
            #pragma unroll
            for (int mt = 0; mt < 4; mt++)
                #pragma unroll
                for (int nt = 0; nt < 4; nt++) {
                    MMA_F16(c[mt][nt], a[mt], bh[nt]);
                    MMA_F16(c[mt][nt], a[mt], bl[nt]);
                }
        }
        __syncthreads();
    }

    #pragma unroll
    for (int mt = 0; mt < 4; mt++) {
        #pragma unroll
        for (int nt = 0; nt < 4; nt++) {
            int row = m0 + wm * 64 + mt * 16 + (lane >> 2);
            int col = n0 + wn * 32 + nt * 8 + (lane & 3) * 2;
            if (act == 3) {
                #pragma unroll
                for (int pr = 0; pr < 2; pr++) {
                    int gm = row + pr * 8;
                    if (gm >= M) continue;
                    float v0 = c[mt][nt][pr * 2];
                    float v1 = c[mt][nt][pr * 2 + 1];
                    int i2 = (col & (HD_ - 1)) >> 1;
                    int sPos = gm & (S_ - 1);
                    float freq = expf(((float)(2 * i2) / (float)HD_) * -9.210340371976184f);
                    float sn, cs; sincosf((float)sPos * freq, &sn, &cs);
                    float r0 = v0 * cs - v1 * sn;
                    float r1 = v0 * sn + v1 * cs;
                    size_t ci = (size_t)gm * ldc + col;
                    unsigned ulo;
                    unsigned uhi = pack2(r0, r1, ulo);
                    *(unsigned*)(Ch + ci) = uhi;
                    *(unsigned*)(Cl + ci) = ulo;
                }
            } else if (Cf) {
                #pragma unroll
                for (int pr = 0; pr < 2; pr++) {
                    int gm = row + pr * 8;
                    if (gm >= M) continue;
                    float v0 = c[mt][nt][pr * 2];
                    float v1 = c[mt][nt][pr * 2 + 1];
                    size_t ci = (size_t)gm * ldc + col;
                    if (act == 2) {
                        float g0 = C[ci], g1 = C[ci + 1];
                        v0 *= g0 / (1.f + expf(-g0));
                        v1 *= g1 / (1.f + expf(-g1));
                    }
                    *(unsigned*)(Cf + ci) = packh(v0, v1);
                }
            } else {
                #pragma unroll
                for (int t = 0; t < 4; t++) {
                    int gm = row + (t >> 1) * 8;
                    int gn = col + (t & 1);
                    if (gm >= M || gn >= N) continue;
                    float vv = c[mt][nt][t] * alpha;
                    size_t ci = (size_t)gm * ldc + gn;
                    if (accum) vv += C[ci];
                    C[ci] = vv;
                }
            }
        }
    }
}

// ---------------- vectorized transpose + split: fp32 [K][N] -> [N][K] hi/lo ----------------
__global__ void tsplit_kernel(const float* __restrict__ src, bf16* __restrict__ hi,
                              bf16* __restrict__ lo, int K, int N) {
    __shared__ float t[32][33];
    size_t off = (size_t)blockIdx.z * K * N;
    int n0 = blockIdx.x * 32, k0 = blockIdx.y * 32;
    int tid = threadIdx.x;
    #pragma unroll
    for (int i = 0; i < 2; i++) {
        int r = tid + i * 128;                 // 0..255
        int kR = r >> 3, c4 = (r & 7) * 4;
        float4 vv = *(const float4*)(src + off + (size_t)(k0 + kR) * N + n0 + c4);
        t[kR][c4] = vv.x; t[kR][c4+1] = vv.y; t[kR][c4+2] = vv.z; t[kR][c4+3] = vv.w;
    }
    __syncthreads();
    int n = tid >> 2, k8 = (tid & 3) * 8;
    unsigned uh[4], ul[4];
    #pragma unroll
    for (int j = 0; j < 4; j++)
        uh[j] = pack2(t[k8 + 2*j][n], t[k8 + 2*j + 1][n], ul[j]);
    size_t o = off + (size_t)(n0 + n) * K + k0 + k8;
    *(uint4*)(hi + o) = make_uint4(uh[0], uh[1], uh[2], uh[3]);
    *(uint4*)(lo + o) = make_uint4(ul[0], ul[1], ul[2], ul[3]);
}

__global__ void tsplit_f16_kernel(const float* __restrict__ src, f16* __restrict__ hi,
                                  f16* __restrict__ lo, int K, int N) {
    __shared__ float t[32][33];
    size_t off = (size_t)blockIdx.z * K * N;
    int n0 = blockIdx.x * 32, k0 = blockIdx.y * 32;
    int tid = threadIdx.x;
    #pragma unroll
    for (int i = 0; i < 2; i++) {
        int r = tid + i * 128;
        int kR = r >> 3, c4 = (r & 7) * 4;
        float4 vv = *(const float4*)(src + off + (size_t)(k0 + kR) * N + n0 + c4);
        t[kR][c4] = vv.x; t[kR][c4+1] = vv.y; t[kR][c4+2] = vv.z; t[kR][c4+3] = vv.w;
    }
    __syncthreads();
    int n = tid >> 2, k8 = (tid & 3) * 8;
    unsigned uh[4], ul[4];
    #pragma unroll
    for (int j = 0; j < 4; j++)
        uh[j] = pack2f(t[k8 + 2*j][n], t[k8 + 2*j + 1][n], ul[j]);
    size_t o = off + (size_t)(n0 + n) * K + k0 + k8;
    *(uint4*)(hi + o) = make_uint4(uh[0], uh[1], uh[2], uh[3]);
    *(uint4*)(lo + o) = make_uint4(ul[0], ul[1], ul[2], ul[3]);
}

// ---------------- elementwise / norm kernels ----------------
__global__ void split_kernel(const float* __restrict__ src, bf16* __restrict__ hi,
                             bf16* __restrict__ lo, size_t n) {
    size_t i = ((size_t)blockIdx.x * blockDim.x + threadIdx.x) * 4;
    if (i + 3 < n) {
        float4 v = *(const float4*)(src + i);
        split2(v.x, hi + i,     lo + i);
        split2(v.y, hi + i + 1, lo + i + 1);
        split2(v.z, hi + i + 2, lo + i + 2);
        split2(v.w, hi + i + 3, lo + i + 3);
    } else {
        for (; i < n; i++) split2(src[i], hi + i, lo + i);
    }
}

__global__ void gelu_bias_pair_kernel(bf16* hh, bf16* hl, const float* __restrict__ b, int n) {
    int i = blockIdx.x * blockDim.x + threadIdx.x;
    if (i >= n) return;
    float v = __bfloat162float(hh[i]) + __bfloat162float(hl[i]) + b[i % HID_];
    v = 0.5f * v * (1.f + erff(v * 0.70710678118654752f));
    split2(v, hh + i, hl + i);
}

__global__ void bias_add_kernel(float* x, const float* __restrict__ b, int n, int cols) {
    int i = blockIdx.x * blockDim.x + threadIdx.x;
    if (i >= n) return;
    x[i] += b[i % cols];
}

__global__ void rmsnorm_f16_kernel(const float* __restrict__ x, const float* __restrict__ w,
                                   f16* __restrict__ o) {
    size_t row = blockIdx.x;
    const float* xr = x + row * D_;
    float s = 0.f;
    for (int i = threadIdx.x; i < D_; i += blockDim.x) { float v = xr[i]; s += v * v; }
    s = blockReduceSum(s);
    float inv = rsqrtf(s / (float)D_ + EPS_);
    for (int i = threadIdx.x; i < D_; i += blockDim.x)
        o[row * D_ + i] = __float2half_rn(xr[i] * inv * w[i]);
}

__global__ void layernorm_kernel(float* __restrict__ x, const float* __restrict__ g,
                                 const float* __restrict__ b) {
    size_t row = blockIdx.x;
    float* xr = x + row * D_;
    float s = 0.f;
    for (int i = threadIdx.x; i < D_; i += blockDim.x) s += xr[i];
    s = blockReduceSum(s);
    float mu = s / (float)D_;
    float s2 = 0.f;
    for (int i = threadIdx.x; i < D_; i += blockDim.x) { float d = xr[i] - mu; s2 += d * d; }
    s2 = blockReduceSum(s2);
    float inv = rsqrtf(s2 / (float)D_ + EPS_);
    for (int i = threadIdx.x; i < D_; i += blockDim.x)
        xr[i] = (xr[i] - mu) * inv * g[i] + b[i];
}

__global__ void embed_kernel(const int* __restrict__ ids, const int* __restrict__ pos,
                             const float* __restrict__ tok_emb, const float* __restrict__ spec,
                             float* __restrict__ h) {
    int bs = blockIdx.x;
    int b = bs / S_, s = bs % S_;
    int p = pos[b];
    const float* src;
    if (s >= p && s < p + K_) src = spec + ((size_t)b * K_ + (s - p)) * D_;
    else                      src = tok_emb + (size_t)ids[bs] * D_;
    float* dst = h + (size_t)bs * D_;
    for (int i = threadIdx.x; i < D_; i += blockDim.x) dst[i] = src[i];
}

__global__ void softmax_split_kernel(const float* __restrict__ sc,
                                     bf16* __restrict__ ph, bf16* __restrict__ pl) {
    size_t row = blockIdx.x;
    int q = (int)(row % S_);
    const float* r = sc + row * (size_t)S_;
    bf16* oh = ph + row * (size_t)S_;
    bf16* ol = pl + row * (size_t)S_;
    int n = q + 1;
    float mx = -3.4e38f;
    for (int j = threadIdx.x; j < n; j += blockDim.x) mx = fmaxf(mx, r[j]);
    mx = blockReduceMax(mx);
    float sum = 0.f;
    for (int j = threadIdx.x; j < n; j += blockDim.x) sum += expf(r[j] - mx);
    sum = blockReduceSum(sum);
    float inv = 1.f / sum;
    for (int j = threadIdx.x; j < n; j += blockDim.x)
        split2(expf(r[j] - mx) * inv, oh + j, ol + j);
    int zend = ((q >> 7) + 1) << 7;
    if (zend > S_) zend = S_;
    for (int j = n + threadIdx.x; j < zend; j += blockDim.x) {
        oh[j] = __float2bfloat16(0.f);
        ol[j] = __float2bfloat16(0.f);
    }
}

// ---------------- host side ----------------
static void launch_bgemm(const bf16* Ah, const bf16* Al, const bf16* Bh, const bf16* Bl,
                         float* C, bf16* Ch, bf16* Cl, f16* Cf,
                         int M, int N, int Kd, int lda, int ldb, int ldc,
                         long long sA1, long long sA2, long long sB1, long long sB2,
                         long long sC1, long long sC2,
                         int nb2, int bDiv, int nz, float alpha, int accum,
                         int cs, int ck)
{
    dim3 grid((N + BN - 1) / BN, (M + BM - 1) / BM, nz);
    gemm_bf16_kernel<<<grid, 256, SMEM_BYTES>>>(Ah, Al, Bh, Bl, C, Ch, Cl, Cf,
                                                M, N, Kd, lda, ldb, ldc,
                                                sA1, sA2, sB1, sB2, sC1, sC2,
                                                nb2, bDiv, alpha, accum, cs, ck);
}

static void launch_fgemm(const f16* A, const f16* Bh, const f16* Bl,
                         float* C, bf16* Ch, bf16* Cl, f16* Cf,
                         int M, int N, int Kd, int lda, int ldb, int ldc,
                         float alpha, int act, int accum)
{
    dim3 grid((M + BM - 1) / BM, N / BN, 1);   // M fastest
    gemm_f16_kernel<<<grid, 256, SMEM_F_BYTES>>>(A, Bh, Bl, C, Ch, Cl, Cf,
                                                 M, N, Kd, lda, ldb, ldc,
                                                 alpha, act, accum);
}

static void launch_tsplit(const float* src, bf16* hi, bf16* lo, int K, int N, int nz) {
    dim3 grid(N / 32, K / 32, nz);
    tsplit_kernel<<<grid, 128>>>(src, hi, lo, K, N);
}
static void launch_tsplit_f16(const float* src, f16* hi, f16* lo, int K, int N, int nz) {
    dim3 grid(N / 32, K / 32, nz);
    tsplit_f16_kernel<<<grid, 128>>>(src, hi, lo, K, N);
}
static void launch_split(const float* src, bf16* hi, bf16* lo, size_t n) {
    unsigned g = (unsigned)((n / 4 + 255) / 256);
    split_kernel<<<g, 256>>>(src, hi, lo, n);
}

#define SYM(p, s) cudaGetSymbolAddress((void**)&p, s)

extern "C" void kernel_launch(void* const* d_in, const int* in_sizes, int n_in,
                              void* d_out, int out_size) {
    cudaFuncSetAttribute(gemm_bf16_kernel,
                         cudaFuncAttributeMaxDynamicSharedMemorySize, SMEM_BYTES);
    cudaFuncSetAttribute(gemm_f16_kernel,
                         cudaFuncAttributeMaxDynamicSharedMemorySize, SMEM_F_BYTES);

    const int*   input_ids = (const int*)  d_in[0];
    const float* spectra   = (const float*)d_in[1];
    const int*   spos      = (const int*)  d_in[2];
    const float* proj_w1   = (const float*)d_in[3];
    const float* proj_b1   = (const float*)d_in[4];
    const float* proj_w2   = (const float*)d_in[5];
    const float* proj_b2   = (const float*)d_in[6];
    const float* proj_ln_g = (const float*)d_in[7];
    const float* proj_ln_b = (const float*)d_in[8];
    const float* tok_emb   = (const float*)d_in[9];
    const float* attn_norm = (const float*)d_in[10];
    const float* wq        = (const float*)d_in[11];
    const float* wk        = (const float*)d_in[12];
    const float* wv        = (const float*)d_in[13];
    const float* wo        = (const float*)d_in[14];
    const float* ffn_norm  = (const float*)d_in[15];
    const float* w1        = (const float*)d_in[16];
    const float* w3        = (const float*)d_in[17];
    const float* w2        = (const float*)d_in[18];
    const float* norm_w    = (const float*)d_in[19];
    const float* out_w     = (const float*)d_in[20];
    float* out = (float*)d_out;

    float *h, *v, *sc, *f1, *spec;
    SYM(h, g_h); SYM(v, g_v); SYM(sc, g_sc); SYM(f1, g_f1); SYM(spec, g_spec);

    f16 *xf, *atf, *ff;
    SYM(xf, s_xf); SYM(atf, s_atf); SYM(ff, s_ff);

    bf16 *qh,*ql,*kh,*kl,*vth,*vtl,*ph,*pl,*h1h,*h1l,*sph,*spl;
    SYM(qh, s_qh); SYM(ql, s_ql); SYM(kh, s_kh); SYM(kl, s_kl);
    SYM(vth, s_vth); SYM(vtl, s_vtl); SYM(ph, s_ph); SYM(pl, s_pl);
    SYM(h1h, s_h1h); SYM(h1l, s_h1l); SYM(sph, s_sph); SYM(spl, s_spl);

    bf16 *pw1h,*pw1l,*pw2h,*pw2l;
    SYM(pw1h, w_pw1h); SYM(pw1l, w_pw1l); SYM(pw2h, w_pw2h); SYM(pw2l, w_pw2l);
    f16 *wqh,*wql,*wkh,*wkl,*wvh,*wvl,*woh,*wol,*w1h,*w1l,*w3h,*w3l,*w2h,*w2l,*owh,*owl;
    SYM(wqh, w_qh); SYM(wql, w_ql); SYM(wkh, w_kh); SYM(wkl, w_kl);
    SYM(wvh, w_vh); SYM(wvl, w_vl); SYM(woh, w_oh); SYM(wol, w_ol);
    SYM(w1h, w_1h); SYM(w1l, w_1l); SYM(w3h, w_3h); SYM(w3l, w_3l);
    SYM(w2h, w_2h); SYM(w2l, w_2l); SYM(owh, w_owh); SYM(owl, w_owl);

    // ---- weight conversions ----
    launch_tsplit(proj_w1, pw1h, pw1l, LAT_, HID_, 1);
    launch_tsplit(proj_w2, pw2h, pw2l, HID_, K_*D_, 1);
    launch_tsplit_f16(wq, wqh, wql, D_, D_, 2);
    launch_tsplit_f16(wk, wkh, wkl, D_, NKV_*HD_, 2);
    launch_tsplit_f16(wv, wvh, wvl, D_, NKV_*HD_, 2);
    launch_tsplit_f16(wo, woh, wol, D_, D_, 2);
    launch_tsplit_f16(w1, w1h, w1l, D_, FFN_, 2);
    launch_tsplit_f16(w3, w3h, w3l, D_, FFN_, 2);
    launch_tsplit_f16(w2, w2h, w2l, FFN_, D_, 2);
    launch_tsplit_f16(out_w, owh, owl, D_, V_, 1);
    launch_split(spectra, sph, spl, (size_t)B_*LAT_);

    // ---- spectral projection (bf16 3-term; tiny M) ----
    launch_bgemm(sph, spl, pw1h, pw1l, nullptr, h1h, h1l, nullptr,
                 B_, HID_, LAT_, LAT_, LAT_, HID_, 0,0,0,0,0,0, 1,1,1, 1.f, 0, 0, 0);
    gelu_bias_pair_kernel<<<(B_*HID_ + 255)/256, 256>>>(h1h, h1l, proj_b1, B_*HID_);
    launch_bgemm(h1h, h1l, pw2h, pw2l, spec, nullptr, nullptr, nullptr,
                 B_, K_*D_, HID_, HID_, HID_, K_*D_, 0,0,0,0,0,0, 1,1,1, 1.f, 0, 0, 0);
    bias_add_kernel<<<(B_*K_*D_ + 255)/256, 256>>>(spec, proj_b2, B_*K_*D_, K_*D_);
    layernorm_kernel<<<B_*K_, 256>>>(spec, proj_ln_g, proj_ln_b);

    embed_kernel<<<B_*S_, 256>>>(input_ids, spos, tok_emb, spec, h);

    const float inv_sqrt_hd = 0.08838834764831845f;
    const int M = B_*S_;

    for (int l = 0; l < 2; l++) {
        const f16 *Wqh = wqh + (size_t)l*D_*D_,        *Wql = wql + (size_t)l*D_*D_;
        const f16 *Wkh = wkh + (size_t)l*NKV_*HD_*D_,  *Wkl = wkl + (size_t)l*NKV_*HD_*D_;
        const f16 *Wvh = wvh + (size_t)l*NKV_*HD_*D_,  *Wvl = wvl + (size_t)l*NKV_*HD_*D_;
        const f16 *Woh = woh + (size_t)l*D_*D_,        *Wol = wol + (size_t)l*D_*D_;
        const f16 *W1h = w1h + (size_t)l*FFN_*D_,      *W1l = w1l + (size_t)l*FFN_*D_;
        const f16 *W3h = w3h + (size_t)l*FFN_*D_,      *W3l = w3l + (size_t)l*FFN_*D_;
        const f16 *W2h = w2h + (size_t)l*D_*FFN_,      *W2l = w2l + (size_t)l*D_*FFN_;

        rmsnorm_f16_kernel<<<M, 256>>>(h, attn_norm + (size_t)l*D_, xf);

        launch_fgemm(xf, Wqh, Wql, nullptr, qh, ql, nullptr,
                     M, D_, D_, D_, D_, D_, 1.f, 3, 0);
        launch_fgemm(xf, Wkh, Wkl, nullptr, kh, kl, nullptr,
                     M, NKV_*HD_, D_, D_, D_, NKV_*HD_, 1.f, 3, 0);
        launch_fgemm(xf, Wvh, Wvl, v, nullptr, nullptr, nullptr,
                     M, NKV_*HD_, D_, D_, D_, NKV_*HD_, 1.f, 0, 0);

        launch_tsplit(v, vth, vtl, S_, NKV_*HD_, B_);

        launch_bgemm(qh, ql, kh, kl, sc, nullptr, nullptr, nullptr,
                     S_, S_, HD_, D_, NKV_*HD_, S_,
                     (long long)S_*D_, (long long)HD_,
                     (long long)S_*NKV_*HD_, (long long)HD_,
                     (long long)NH_*S_*S_, (long long)S_*S_,
                     NH_, NREP_, B_*NH_, inv_sqrt_hd, 0, 1, 0);

        softmax_split_kernel<<<B_*NH_*S_, 128>>>(sc, ph, pl);

        launch_bgemm(ph, pl, vth, vtl, nullptr, nullptr, nullptr, atf,
                     S_, HD_, S_, S_, S_, D_,
                     (long long)NH_*S_*S_, (long long)S_*S_,
                     (long long)NKV_*HD_*S_, (long long)HD_*S_,
                     (long long)S_*D_, (long long)HD_,
                     NH_, NREP_, B_*NH_, 1.f, 0, 0, 1);

        launch_fgemm(atf, Woh, Wol, h, nullptr, nullptr, nullptr,
                     M, D_, D_, D_, D_, D_, 1.f, 0, 1);

        rmsnorm_f16_kernel<<<M, 256>>>(h, ffn_norm + (size_t)l*D_, xf);
        launch_fgemm(xf, W1h, W1l, f1, nullptr, nullptr, nullptr,
                     M, FFN_, D_, D_, D_, FFN_, 1.f, 0, 0);
        launch_fgemm(xf, W3h, W3l, f1, nullptr, nullptr, ff,
                     M, FFN_, D_, D_, D_, FFN_, 1.f, 2, 0);
        launch_fgemm(ff, W2h, W2l, h, nullptr, nullptr, nullptr,
                     M, D_, FFN_, FFN_, FFN_, D_, 1.f, 0, 1);
    }

    rmsnorm_f16_kernel<<<M, 256>>>(h, norm_w, xf);
    launch_fgemm(xf, owh, owl, out, nullptr, nullptr, nullptr,
                 M, V_, D_, D_, D_, V_, 1.f, 0, 0);
}

// round 17
// speedup vs baseline: 1.0295x; 1.0295x over previous
#include <cuda_runtime.h>
#include <cuda_bf16.h>
#include <cuda_fp16.h>
#include <stdint.h>
#include <math.h>

#define B_   4
#define S_   1024
#define D_   2048
#define NH_  16
#define NKV_ 8
#define HD_  128
#define NREP_ 2
#define K_   8
#define FFN_ 5632
#define V_   32000
#define LAT_ 1024
#define HID_ 2048
#define EPS_ 1e-5f

typedef __nv_bfloat16 bf16;
typedef __half f16;

// ---------------- fp32 scratch ----------------
__device__ float g_h   [B_*S_*D_];
__device__ float g_v   [B_*S_*NKV_*HD_];
__device__ float g_sc  [(size_t)B_*NH_*S_*S_];
__device__ float g_spec[B_*K_*D_];

// ---------------- activation scratch ----------------
__device__ f16  s_xf [B_*S_*D_];
__device__ f16  s_atf[B_*S_*D_];
__device__ f16  s_ff [B_*S_*FFN_];
__device__ bf16 s_qh [B_*S_*D_],        s_ql [B_*S_*D_];
__device__ bf16 s_kh [B_*S_*NKV_*HD_],  s_kl [B_*S_*NKV_*HD_];
__device__ bf16 s_vth[B_*NKV_*HD_*S_],  s_vtl[B_*NKV_*HD_*S_];
__device__ bf16 s_ph [(size_t)B_*NH_*S_*S_], s_pl [(size_t)B_*NH_*S_*S_];
__device__ bf16 s_h1h[B_*HID_],         s_h1l[B_*HID_];
__device__ bf16 s_sph[B_*LAT_],         s_spl[B_*LAT_];

// ---------------- transposed weights [N][K] ----------------
__device__ bf16 w_pw1h[HID_*LAT_],      w_pw1l[HID_*LAT_];
__device__ bf16 w_pw2h[K_*D_*HID_],     w_pw2l[K_*D_*HID_];
__device__ f16  w_qh [2*D_*D_],         w_ql [2*D_*D_];
__device__ f16  w_kh [2*NKV_*HD_*D_],   w_kl [2*NKV_*HD_*D_];
__device__ f16  w_vh [2*NKV_*HD_*D_],   w_vl [2*NKV_*HD_*D_];
__device__ f16  w_oh [2*D_*D_],         w_ol [2*D_*D_];
__device__ f16  w_13h[2*(size_t)2*FFN_*D_], w_13l[2*(size_t)2*FFN_*D_];  // interleaved W1/W3
__device__ f16  w_2h [2*D_*FFN_],       w_2l [2*D_*FFN_];
__device__ f16  w_owh[(size_t)V_*D_],   w_owl[(size_t)V_*D_];

// ---------------- reductions ----------------
__device__ __forceinline__ float blockReduceSum(float v) {
    __shared__ float sh[32];
    __syncthreads();
    int lane = threadIdx.x & 31, wid = threadIdx.x >> 5;
    #pragma unroll
    for (int o = 16; o; o >>= 1) v += __shfl_down_sync(0xffffffffu, v, o);
    if (lane == 0) sh[wid] = v;
    __syncthreads();
    int nw = (blockDim.x + 31) >> 5;
    v = (threadIdx.x < nw) ? sh[threadIdx.x] : 0.f;
    if (wid == 0) {
        #pragma unroll
        for (int o = 16; o; o >>= 1) v += __shfl_down_sync(0xffffffffu, v, o);
        if (lane == 0) sh[0] = v;
    }
    __syncthreads();
    return sh[0];
}
__device__ __forceinline__ float blockReduceMax(float v) {
    __shared__ float sh[32];
    __syncthreads();
    int lane = threadIdx.x & 31, wid = threadIdx.x >> 5;
    #pragma unroll
    for (int o = 16; o; o >>= 1) v = fmaxf(v, __shfl_down_sync(0xffffffffu, v, o));
    if (lane == 0) sh[wid] = v;
    __syncthreads();
    int nw = (blockDim.x + 31) >> 5;
    v = (threadIdx.x < nw) ? sh[threadIdx.x] : -3.4e38f;
    if (wid == 0) {
        #pragma unroll
        for (int o = 16; o; o >>= 1) v = fmaxf(v, __shfl_down_sync(0xffffffffu, v, o));
        if (lane == 0) sh[0] = v;
    }
    __syncthreads();
    return sh[0];
}
__device__ __forceinline__ void split2(float v, bf16* hp, bf16* lp) {
    bf16 hi = __float2bfloat16(v);
    *hp = hi;
    *lp = __float2bfloat16(v - __bfloat162float(hi));
}
__device__ __forceinline__ unsigned pack2(float v0, float v1, unsigned &ulo) {
    bf16 h0 = __float2bfloat16(v0);
    bf16 l0 = __float2bfloat16(v0 - __bfloat162float(h0));
    bf16 h1 = __float2bfloat16(v1);
    bf16 l1 = __float2bfloat16(v1 - __bfloat162float(h1));
    ulo = (unsigned)__bfloat16_as_ushort(l0) | ((unsigned)__bfloat16_as_ushort(l1) << 16);
    return (unsigned)__bfloat16_as_ushort(h0) | ((unsigned)__bfloat16_as_ushort(h1) << 16);
}
__device__ __forceinline__ unsigned pack2f(float v0, float v1, unsigned &ulo) {
    f16 h0 = __float2half_rn(v0);
    f16 l0 = __float2half_rn(v0 - __half2float(h0));
    f16 h1 = __float2half_rn(v1);
    f16 l1 = __float2half_rn(v1 - __half2float(h1));
    ulo = (unsigned)__half_as_ushort(l0) | ((unsigned)__half_as_ushort(l1) << 16);
    return (unsigned)__half_as_ushort(h0) | ((unsigned)__half_as_ushort(h1) << 16);
}
__device__ __forceinline__ unsigned packh(float v0, float v1) {
    return (unsigned)__half_as_ushort(__float2half_rn(v0)) |
           ((unsigned)__half_as_ushort(__float2half_rn(v1)) << 16);
}

// ---------------- tiling constants ----------------
#define BM 128
#define BN 128
#define BK 32
#define LDS_ROW 40
#define TILE_H (BM * LDS_ROW)
#define STAGE_H (4 * TILE_H)
#define SMEM_BYTES (2 * STAGE_H * 2)        // bf16 3-term, 2-stage: 81920
#define STAGE_F_H (3 * TILE_H)
#define SMEM_F_BYTES (3 * STAGE_F_H * 2)    // fp16 2-term, 3-stage: 92160

#define MMA_BF16(d, a, b)                                                          \
    asm volatile("mma.sync.aligned.m16n8k16.row.col.f32.bf16.bf16.f32 "            \
                 "{%0,%1,%2,%3},{%4,%5,%6,%7},{%8,%9},{%0,%1,%2,%3};"              \
                 : "+f"(d[0]), "+f"(d[1]), "+f"(d[2]), "+f"(d[3])                  \
                 : "r"(a[0]), "r"(a[1]), "r"(a[2]), "r"(a[3]), "r"(b[0]), "r"(b[1]))

#define MMA_F16(d, a, b)                                                           \
    asm volatile("mma.sync.aligned.m16n8k16.row.col.f32.f16.f16.f32 "              \
                 "{%0,%1,%2,%3},{%4,%5,%6,%7},{%8,%9},{%0,%1,%2,%3};"              \
                 : "+f"(d[0]), "+f"(d[1]), "+f"(d[2]), "+f"(d[3])                  \
                 : "r"(a[0]), "r"(a[1]), "r"(a[2]), "r"(a[3]), "r"(b[0]), "r"(b[1]))

#define LDSM_X4(r0, r1, r2, r3, a)                                                 \
    asm volatile("ldmatrix.sync.aligned.m8n8.x4.shared.b16 {%0,%1,%2,%3}, [%4];"   \
                 : "=r"(r0), "=r"(r1), "=r"(r2), "=r"(r3) : "r"(a))

__device__ __forceinline__ void cpasync16(uint32_t dst, const void* src, int srcBytes) {
    asm volatile("cp.async.cg.shared.global [%0], [%1], 16, %2;"
                 :: "r"(dst), "l"(src), "r"(srcBytes));
}

// ================= GEMM (bf16 3-term, 2-stage) — attention / spectral path =================
__global__ void __launch_bounds__(256)
gemm_bf16_kernel(const bf16* __restrict__ Ah, const bf16* __restrict__ Al,
                 const bf16* __restrict__ Bh, const bf16* __restrict__ Bl,
                 float* __restrict__ C, bf16* __restrict__ Ch, bf16* __restrict__ Cl,
                 f16* __restrict__ Cf,
                 int M, int N, int Kd, int lda, int ldb, int ldc,
                 long long sA1, long long sA2, long long sB1, long long sB2,
                 long long sC1, long long sC2,
                 int nb2, int bDiv, float alpha, int accum,
                 int causalSkip, int causalK)
{
    int m0 = blockIdx.y * BM, n0 = blockIdx.x * BN;
    if (causalSkip && n0 >= m0 + BM) return;

    int z = blockIdx.z;
    int b1 = z / nb2, b2 = z % nb2;
    size_t offA = (size_t)b1 * sA1 + (size_t)b2 * sA2;
    size_t offB = (size_t)b1 * sB1 + (size_t)(b2 / bDiv) * sB2;
    size_t offC = (size_t)b1 * sC1 + (size_t)b2 * sC2;
    Ah += offA; Al += offA; Bh += offB; Bl += offB;

    int Klim = (causalK && m0 + BM < Kd) ? (m0 + BM) : Kd;
    int nk = Klim / BK;

    extern __shared__ bf16 smem[];
    uint32_t sbase = (uint32_t)__cvta_generic_to_shared(smem);

    int tid  = threadIdx.x;
    int lane = tid & 31;
    int warp = tid >> 5;
    int wm = warp >> 2, wn = warp & 3;

    int aRow = wm * 64 + (lane & 15);
    int aCol = (lane >> 4) << 3;
    int bRow = wn * 32 + ((lane >> 4) << 3) + (lane & 7);
    int bCol = (lane & 8);

    float c[4][4][4];
    #pragma unroll
    for (int i = 0; i < 4; i++)
        #pragma unroll
        for (int j = 0; j < 4; j++)
            #pragma unroll
            for (int t = 0; t < 4; t++) c[i][j][t] = 0.f;

    auto copyStage = [&](int kt) {
        uint32_t s0 = sbase + (uint32_t)(kt & 1) * STAGE_H * 2;
        int k0 = kt * BK;
        #pragma unroll
        for (int i = 0; i < 2; i++) {
            int cid = tid + i * 256;
            int row = cid >> 2, kc = (cid & 3) * 8;
            size_t go = (size_t)(m0 + row) * lda + k0 + kc;
            int pm = ((m0 + row) < M) ? 16 : 0;
            uint32_t da = s0 + (uint32_t)(row * LDS_ROW + kc) * 2;
            cpasync16(da,               Ah + go, pm);
            cpasync16(da + TILE_H * 2,  Al + go, pm);
            size_t gb = (size_t)(n0 + row) * ldb + k0 + kc;
            uint32_t db = s0 + (uint32_t)(2 * TILE_H + row * LDS_ROW + kc) * 2;
            cpasync16(db,               Bh + gb, 16);
            cpasync16(db + TILE_H * 2,  Bl + gb, 16);
        }
        asm volatile("cp.async.commit_group;");
    };

    copyStage(0);
    for (int kt = 0; kt < nk; kt++) {
        asm volatile("cp.async.wait_group 0;");
        __syncthreads();
        if (kt + 1 < nk) copyStage(kt + 1);

        uint32_t s0 = sbase + (uint32_t)(kt & 1) * STAGE_H * 2;

        #pragma unroll
        for (int s = 0; s < 2; s++) {
            int kc = s * 16;
            unsigned ah[4][4], al[4][4], bh[4][2], bl[4][2];
            #pragma unroll
            for (int mt = 0; mt < 4; mt++) {
                uint32_t adr = s0 + (uint32_t)((aRow + mt * 16) * LDS_ROW + kc + aCol) * 2;
                LDSM_X4(ah[mt][0], ah[mt][1], ah[mt][2], ah[mt][3], adr);
                LDSM_X4(al[mt][0], al[mt][1], al[mt][2], al[mt][3], adr + TILE_H * 2);
            }
            #pragma unroll
            for (int p = 0; p < 2; p++) {
                uint32_t adr = s0 + (uint32_t)(2 * TILE_H + (bRow + p * 16) * LDS_ROW + kc + bCol) * 2;
                unsigned r0, r1, r2, r3;
                LDSM_X4(r0, r1, r2, r3, adr);
                bh[2*p][0] = r0; bh[2*p][1] = r1; bh[2*p+1][0] = r2; bh[2*p+1][1] = r3;
                LDSM_X4(r0, r1, r2, r3, adr + TILE_H * 2);
                bl[2*p][0] = r0; bl[2*p][1] = r1; bl[2*p+1][0] = r2; bl[2*p+1][1] = r3;
            }
            #pragma unroll
            for (int mt = 0; mt < 4; mt++)
                #pragma unroll
                for (int nt = 0; nt < 4; nt++) {
                    MMA_BF16(c[mt][nt], ah[mt], bh[nt]);
                    MMA_BF16(c[mt][nt], ah[mt], bl[nt]);
                    MMA_BF16(c[mt][nt], al[mt], bh[nt]);
                }
        }
        __syncthreads();
    }

    #pragma unroll
    for (int mt = 0; mt < 4; mt++) {
        #pragma unroll
        for (int nt = 0; nt < 4; nt++) {
            int row = m0 + wm * 64 + mt * 16 + (lane >> 2);
            int col = n0 + wn * 32 + nt * 8 + (lane & 3) * 2;
            if (Cf || Ch) {
                #pragma unroll
                for (int pr = 0; pr < 2; pr++) {
                    int gm = row + pr * 8;
                    if (gm >= M) continue;
                    float v0 = c[mt][nt][pr * 2]     * alpha;
                    float v1 = c[mt][nt][pr * 2 + 1] * alpha;
                    size_t ci = offC + (size_t)gm * ldc + col;
                    if (Cf) {
                        *(unsigned*)(Cf + ci) = packh(v0, v1);
                    } else {
                        unsigned ulo;
                        unsigned uhi = pack2(v0, v1, ulo);
                        *(unsigned*)(Ch + ci) = uhi;
                        *(unsigned*)(Cl + ci) = ulo;
                    }
                }
            } else {
                #pragma unroll
                for (int t = 0; t < 4; t++) {
                    int gm = row + (t >> 1) * 8;
                    int gn = col + (t & 1);
                    if (gm >= M || gn >= N) continue;
                    float vv = c[mt][nt][t] * alpha;
                    size_t ci = offC + (size_t)gm * ldc + gn;
                    if (accum) vv += C[ci];
                    C[ci] = vv;
                }
            }
        }
    }
}

// ================= GEMM (fp16 2-term, BN=128, 3-stage) — weight path =================
// act: 0=none (fp32 C, optional accum), 3=rope (Ch/Cl bf16 pair out),
//      4=fused swiglu (B rows interleaved W1/W3; even col=gate, odd=value; Cf f16 out, ldc=FFN)
__global__ void __launch_bounds__(256)
gemm_f16_kernel(const f16* __restrict__ A,
                const f16* __restrict__ Bh, const f16* __restrict__ Bl,
                float* __restrict__ C, bf16* __restrict__ Ch, bf16* __restrict__ Cl,
                f16* __restrict__ Cf,
                int M, int N, int Kd, int lda, int ldb, int ldc,
                float alpha, int act, int accum)
{
    int m0 = blockIdx.y * BM, n0 = blockIdx.x * BN;
    int nk = Kd / BK;

    extern __shared__ f16 smemf[];
    uint32_t sbase = (uint32_t)__cvta_generic_to_shared(smemf);

    int tid  = threadIdx.x;
    int lane = tid & 31;
    int warp = tid >> 5;
    int wm = warp >> 2, wn = warp & 3;

    int aRow = wm * 64 + (lane & 15);
    int aCol = (lane >> 4) << 3;
    int bRow = wn * 32 + ((lane >> 4) << 3) + (lane & 7);
    int bCol = (lane & 8);

    float c[4][4][4];
    #pragma unroll
    for (int i = 0; i < 4; i++)
        #pragma unroll
        for (int j = 0; j < 4; j++)
            #pragma unroll
            for (int t = 0; t < 4; t++) c[i][j][t] = 0.f;

    auto copyStage = [&](int kt) {
        int st = kt % 3;
        uint32_t s0 = sbase + (uint32_t)st * STAGE_F_H * 2;
        int k0 = kt * BK;
        #pragma unroll
        for (int i = 0; i < 2; i++) {
            int cid = tid + i * 256;
            int row = cid >> 2, kc = (cid & 3) * 8;
            size_t go = (size_t)(m0 + row) * lda + k0 + kc;
            int pm = ((m0 + row) < M) ? 16 : 0;
            uint32_t da = s0 + (uint32_t)(row * LDS_ROW + kc) * 2;
            cpasync16(da, A + go, pm);
            size_t gb = (size_t)(n0 + row) * ldb + k0 + kc;
            uint32_t db = s0 + (uint32_t)(TILE_H + row * LDS_ROW + kc) * 2;
            cpasync16(db,              Bh + gb, 16);
            cpasync16(db + TILE_H * 2, Bl + gb, 16);
        }
        asm volatile("cp.async.commit_group;");
    };

    copyStage(0);
    if (nk > 1) copyStage(1);
    for (int kt = 0; kt < nk; kt++) {
        if (kt + 1 < nk) asm volatile("cp.async.wait_group 1;");
        else             asm volatile("cp.async.wait_group 0;");
        __syncthreads();
        if (kt + 2 < nk) copyStage(kt + 2);

        uint32_t s0 = sbase + (uint32_t)(kt % 3) * STAGE_F_H * 2;

        #pragma unroll
        for (int s = 0; s < 2; s++) {
            int kc = s * 16;
            unsigned a[4][4], bh[4][2], bl[4][2];
            #pragma unroll
            for (int mt = 0; mt < 4; mt++) {
                uint32_t adr = s0 + (uint32_t)((aRow + mt * 16) * LDS_ROW + kc + aCol) * 2;
                LDSM_X4(a[mt][0], a[mt][1], a[mt][2], a[mt][3], adr);
            }
            #pragma unroll
            for (int p = 0; p < 2; p++) {
                uint32_t adr = s0 + (uint32_t)(TILE_H + (bRow + p * 16) * LDS_ROW + kc + bCol) * 2;
                unsigned r0, r1, r2, r3;
                LDSM_X4(r0, r1, r2, r3, adr);
                bh[2*p][0] = r0; bh[2*p][1] = r1; bh[2*p+1][0] = r2; bh[2*p+1][1] = r3;
                LDSM_X4(r0, r1, r2, r3, adr + TILE_H * 2);
                bl[2*p][0] = r0; bl[2*p][1] = r1; bl[2*p+1][0] = r2; bl[2*p+1][1] = r3;
            }
            #pragma unroll
            for (int mt = 0; mt < 4; mt++)
                #pragma unroll
                for (int nt = 0; nt < 4; nt++) {
                    MMA_F16(c[mt][nt], a[mt], bh[nt]);
                    MMA_F16(c[mt][nt], a[mt], bl[nt]);
                }
        }
        __syncthreads();
    }

    #pragma unroll
    for (int mt = 0; mt < 4; mt++) {
        #pragma unroll
        for (int nt = 0; nt < 4; nt++) {
            int row = m0 + wm * 64 + mt * 16 + (lane >> 2);
            int col = n0 + wn * 32 + nt * 8 + (lane & 3) * 2;
            if (act == 3) {
                #pragma unroll
                for (int pr = 0; pr < 2; pr++) {
                    int gm = row + pr * 8;
                    if (gm >= M) continue;
                    float v0 = c[mt][nt][pr * 2];
                    float v1 = c[mt][nt][pr * 2 + 1];
                    int i2 = (col & (HD_ - 1)) >> 1;
                    int sPos = gm & (S_ - 1);
                    float freq = expf(((float)(2 * i2) / (float)HD_) * -9.210340371976184f);
                    float sn, cs; sincosf((float)sPos * freq, &sn, &cs);
                    float r0 = v0 * cs - v1 * sn;
                    float r1 = v0 * sn + v1 * cs;
                    size_t ci = (size_t)gm * ldc + col;
                    unsigned ulo;
                    unsigned uhi = pack2(r0, r1, ulo);
                    *(unsigned*)(Ch + ci) = uhi;
                    *(unsigned*)(Cl + ci) = ulo;
                }
            } else if (act == 4) {
                // interleaved swiglu: even col = W1 gate, odd col = W3 value
                #pragma unroll
                for (int pr = 0; pr < 2; pr++) {
                    int gm = row + pr * 8;
                    if (gm >= M) continue;
                    float g  = c[mt][nt][pr * 2];
                    float vx = c[mt][nt][pr * 2 + 1];
                    float s  = (g / (1.f + expf(-g))) * vx;
                    Cf[(size_t)gm * ldc + (col >> 1)] = __float2half_rn(s);
                }
            } else if (Cf) {
                #pragma unroll
                for (int pr = 0; pr < 2; pr++) {
                    int gm = row + pr * 8;
                    if (gm >= M) continue;
                    float v0 = c[mt][nt][pr * 2];
                    float v1 = c[mt][nt][pr * 2 + 1];
                    size_t ci = (size_t)gm * ldc + col;
                    *(unsigned*)(Cf + ci) = packh(v0, v1);
                }
            } else {
                #pragma unroll
                for (int t = 0; t < 4; t++) {
                    int gm = row + (t >> 1) * 8;
                    int gn = col + (t & 1);
                    if (gm >= M || gn >= N) continue;
                    float vv = c[mt][nt][t] * alpha;
                    size_t ci = (size_t)gm * ldc + gn;
                    if (accum) vv += C[ci];
                    C[ci] = vv;
                }
            }
        }
    }
}

// ---------------- vectorized transpose + split: fp32 [K][N] -> [N][K] hi/lo ----------------
__global__ void tsplit_kernel(const float* __restrict__ src, bf16* __restrict__ hi,
                              bf16* __restrict__ lo, int K, int N) {
    __shared__ float t[32][33];
    size_t off = (size_t)blockIdx.z * K * N;
    int n0 = blockIdx.x * 32, k0 = blockIdx.y * 32;
    int tid = threadIdx.x;
    #pragma unroll
    for (int i = 0; i < 2; i++) {
        int r = tid + i * 128;
        int kR = r >> 3, c4 = (r & 7) * 4;
        float4 vv = *(const float4*)(src + off + (size_t)(k0 + kR) * N + n0 + c4);
        t[kR][c4] = vv.x; t[kR][c4+1] = vv.y; t[kR][c4+2] = vv.z; t[kR][c4+3] = vv.w;
    }
    __syncthreads();
    int n = tid >> 2, k8 = (tid & 3) * 8;
    unsigned uh[4], ul[4];
    #pragma unroll
    for (int j = 0; j < 4; j++)
        uh[j] = pack2(t[k8 + 2*j][n], t[k8 + 2*j + 1][n], ul[j]);
    size_t o = off + (size_t)(n0 + n) * K + k0 + k8;
    *(uint4*)(hi + o) = make_uint4(uh[0], uh[1], uh[2], uh[3]);
    *(uint4*)(lo + o) = make_uint4(ul[0], ul[1], ul[2], ul[3]);
}

// fp16 variant; dst row index = rowMul*(n0+n) + rowOff, dst layer stride = rowMul*N*K
__global__ void tsplit_f16_kernel(const float* __restrict__ src, f16* __restrict__ hi,
                                  f16* __restrict__ lo, int K, int N,
                                  int rowMul, int rowOff) {
    __shared__ float t[32][33];
    size_t soff = (size_t)blockIdx.z * K * N;
    size_t doff = (size_t)blockIdx.z * (size_t)rowMul * K * N;
    int n0 = blockIdx.x * 32, k0 = blockIdx.y * 32;
    int tid = threadIdx.x;
    #pragma unroll
    for (int i = 0; i < 2; i++) {
        int r = tid + i * 128;
        int kR = r >> 3, c4 = (r & 7) * 4;
        float4 vv = *(const float4*)(src + soff + (size_t)(k0 + kR) * N + n0 + c4);
        t[kR][c4] = vv.x; t[kR][c4+1] = vv.y; t[kR][c4+2] = vv.z; t[kR][c4+3] = vv.w;
    }
    __syncthreads();
    int n = tid >> 2, k8 = (tid & 3) * 8;
    unsigned uh[4], ul[4];
    #pragma unroll
    for (int j = 0; j < 4; j++)
        uh[j] = pack2f(t[k8 + 2*j][n], t[k8 + 2*j + 1][n], ul[j]);
    size_t o = doff + (size_t)(rowMul * (n0 + n) + rowOff) * K + k0 + k8;
    *(uint4*)(hi + o) = make_uint4(uh[0], uh[1], uh[2], uh[3]);
    *(uint4*)(lo + o) = make_uint4(ul[0], ul[1], ul[2], ul[3]);
}

// ---------------- elementwise / norm kernels ----------------
__global__ void split_kernel(const float* __restrict__ src, bf16* __restrict__ hi,
                             bf16* __restrict__ lo, size_t n) {
    size_t i = ((size_t)blockIdx.x * blockDim.x + threadIdx.x) * 4;
    if (i + 3 < n) {
        float4 v = *(const float4*)(src + i);
        split2(v.x, hi + i,     lo + i);
        split2(v.y, hi + i + 1, lo + i + 1);
        split2(v.z, hi + i + 2, lo + i + 2);
        split2(v.w, hi + i + 3, lo + i + 3);
    } else {
        for (; i < n; i++) split2(src[i], hi + i, lo + i);
    }
}

__global__ void gelu_bias_pair_kernel(bf16* hh, bf16* hl, const float* __restrict__ b, int n) {
    int i = blockIdx.x * blockDim.x + threadIdx.x;
    if (i >= n) return;
    float v = __bfloat162float(hh[i]) + __bfloat162float(hl[i]) + b[i % HID_];
    v = 0.5f * v * (1.f + erff(v * 0.70710678118654752f));
    split2(v, hh + i, hl + i);
}

__global__ void bias_add_kernel(float* x, const float* __restrict__ b, int n, int cols) {
    int i = blockIdx.x * blockDim.x + threadIdx.x;
    if (i >= n) return;
    x[i] += b[i % cols];
}

__global__ void rmsnorm_f16_kernel(const float* __restrict__ x, const float* __restrict__ w,
                                   f16* __restrict__ o) {
    size_t row = blockIdx.x;
    const float* xr = x + row * D_;
    float s = 0.f;
    for (int i = threadIdx.x; i < D_; i += blockDim.x) { float v = xr[i]; s += v * v; }
    s = blockReduceSum(s);
    float inv = rsqrtf(s / (float)D_ + EPS_);
    for (int i = threadIdx.x; i < D_; i += blockDim.x)
        o[row * D_ + i] = __float2half_rn(xr[i] * inv * w[i]);
}

__global__ void layernorm_kernel(float* __restrict__ x, const float* __restrict__ g,
                                 const float* __restrict__ b) {
    size_t row = blockIdx.x;
    float* xr = x + row * D_;
    float s = 0.f;
    for (int i = threadIdx.x; i < D_; i += blockDim.x) s += xr[i];
    s = blockReduceSum(s);
    float mu = s / (float)D_;
    float s2 = 0.f;
    for (int i = threadIdx.x; i < D_; i += blockDim.x) { float d = xr[i] - mu; s2 += d * d; }
    s2 = blockReduceSum(s2);
    float inv = rsqrtf(s2 / (float)D_ + EPS_);
    for (int i = threadIdx.x; i < D_; i += blockDim.x)
        xr[i] = (xr[i] - mu) * inv * g[i] + b[i];
}

__global__ void embed_kernel(const int* __restrict__ ids, const int* __restrict__ pos,
                             const float* __restrict__ tok_emb, const float* __restrict__ spec,
                             float* __restrict__ h) {
    int bs = blockIdx.x;
    int b = bs / S_, s = bs % S_;
    int p = pos[b];
    const float* src;
    if (s >= p && s < p + K_) src = spec + ((size_t)b * K_ + (s - p)) * D_;
    else                      src = tok_emb + (size_t)ids[bs] * D_;
    float* dst = h + (size_t)bs * D_;
    for (int i = threadIdx.x; i < D_; i += blockDim.x) dst[i] = src[i];
}

__global__ void softmax_split_kernel(const float* __restrict__ sc,
                                     bf16* __restrict__ ph, bf16* __restrict__ pl) {
    size_t row = blockIdx.x;
    int q = (int)(row % S_);
    const float* r = sc + row * (size_t)S_;
    bf16* oh = ph + row * (size_t)S_;
    bf16* ol = pl + row * (size_t)S_;
    int n = q + 1;
    float mx = -3.4e38f;
    for (int j = threadIdx.x; j < n; j += blockDim.x) mx = fmaxf(mx, r[j]);
    mx = blockReduceMax(mx);
    float sum = 0.f;
    for (int j = threadIdx.x; j < n; j += blockDim.x) sum += expf(r[j] - mx);
    sum = blockReduceSum(sum);
    float inv = 1.f / sum;
    for (int j = threadIdx.x; j < n; j += blockDim.x)
        split2(expf(r[j] - mx) * inv, oh + j, ol + j);
    int zend = ((q >> 7) + 1) << 7;
    if (zend > S_) zend = S_;
    for (int j = n + threadIdx.x; j < zend; j += blockDim.x) {
        oh[j] = __float2bfloat16(0.f);
        ol[j] = __float2bfloat16(0.f);
    }
}

// ---------------- host side ----------------
static void launch_bgemm(const bf16* Ah, const bf16* Al, const bf16* Bh, const bf16* Bl,
                         float* C, bf16* Ch, bf16* Cl, f16* Cf,
                         int M, int N, int Kd, int lda, int ldb, int ldc,
                         long long sA1, long long sA2, long long sB1, long long sB2,
                         long long sC1, long long sC2,
                         int nb2, int bDiv, int nz, float alpha, int accum,
                         int cs, int ck)
{
    dim3 grid((N + BN - 1) / BN, (M + BM - 1) / BM, nz);
    gemm_bf16_kernel<<<grid, 256, SMEM_BYTES>>>(Ah, Al, Bh, Bl, C, Ch, Cl, Cf,
                                                M, N, Kd, lda, ldb, ldc,
                                                sA1, sA2, sB1, sB2, sC1, sC2,
                                                nb2, bDiv, alpha, accum, cs, ck);
}

static void launch_fgemm(const f16* A, const f16* Bh, const f16* Bl,
                         float* C, bf16* Ch, bf16* Cl, f16* Cf,
                         int M, int N, int Kd, int lda, int ldb, int ldc,
                         float alpha, int act, int accum)
{
    dim3 grid(N / BN, (M + BM - 1) / BM, 1);
    gemm_f16_kernel<<<grid, 256, SMEM_F_BYTES>>>(A, Bh, Bl, C, Ch, Cl, Cf,
                                                 M, N, Kd, lda, ldb, ldc,
                                                 alpha, act, accum);
}

static void launch_tsplit(const float* src, bf16* hi, bf16* lo, int K, int N, int nz) {
    dim3 grid(N / 32, K / 32, nz);
    tsplit_kernel<<<grid, 128>>>(src, hi, lo, K, N);
}
static void launch_tsplit_f16(const float* src, f16* hi, f16* lo, int K, int N, int nz,
                              int rowMul = 1, int rowOff = 0) {
    dim3 grid(N / 32, K / 32, nz);
    tsplit_f16_kernel<<<grid, 128>>>(src, hi, lo, K, N, rowMul, rowOff);
}
static void launch_split(const float* src, bf16* hi, bf16* lo, size_t n) {
    unsigned g = (unsigned)((n / 4 + 255) / 256);
    split_kernel<<<g, 256>>>(src, hi, lo, n);
}

#define SYM(p, s) cudaGetSymbolAddress((void**)&p, s)

extern "C" void kernel_launch(void* const* d_in, const int* in_sizes, int n_in,
                              void* d_out, int out_size) {
    cudaFuncSetAttribute(gemm_bf16_kernel,
                         cudaFuncAttributeMaxDynamicSharedMemorySize, SMEM_BYTES);
    cudaFuncSetAttribute(gemm_f16_kernel,
                         cudaFuncAttributeMaxDynamicSharedMemorySize, SMEM_F_BYTES);

    const int*   input_ids = (const int*)  d_in[0];
    const float* spectra   = (const float*)d_in[1];
    const int*   spos      = (const int*)  d_in[2];
    const float* proj_w1   = (const float*)d_in[3];
    const float* proj_b1   = (const float*)d_in[4];
    const float* proj_w2   = (const float*)d_in[5];
    const float* proj_b2   = (const float*)d_in[6];
    const float* proj_ln_g = (const float*)d_in[7];
    const float* proj_ln_b = (const float*)d_in[8];
    const float* tok_emb   = (const float*)d_in[9];
    const float* attn_norm = (const float*)d_in[10];
    const float* wq        = (const float*)d_in[11];
    const float* wk        = (const float*)d_in[12];
    const float* wv        = (const float*)d_in[13];
    const float* wo        = (const float*)d_in[14];
    const float* ffn_norm  = (const float*)d_in[15];
    const float* w1        = (const float*)d_in[16];
    const float* w3        = (const float*)d_in[17];
    const float* w2        = (const float*)d_in[18];
    const float* norm_w    = (const float*)d_in[19];
    const float* out_w     = (const float*)d_in[20];
    float* out = (float*)d_out;

    float *h, *v, *sc, *spec;
    SYM(h, g_h); SYM(v, g_v); SYM(sc, g_sc); SYM(spec, g_spec);

    f16 *xf, *atf, *ff;
    SYM(xf, s_xf); SYM(atf, s_atf); SYM(ff, s_ff);

    bf16 *qh,*ql,*kh,*kl,*vth,*vtl,*ph,*pl,*h1h,*h1l,*sph,*spl;
    SYM(qh, s_qh); SYM(ql, s_ql); SYM(kh, s_kh); SYM(kl, s_kl);
    SYM(vth, s_vth); SYM(vtl, s_vtl); SYM(ph, s_ph); SYM(pl, s_pl);
    SYM(h1h, s_h1h); SYM(h1l, s_h1l); SYM(sph, s_sph); SYM(spl, s_spl);

    bf16 *pw1h,*pw1l,*pw2h,*pw2l;
    SYM(pw1h, w_pw1h); SYM(pw1l, w_pw1l); SYM(pw2h, w_pw2h); SYM(pw2l, w_pw2l);
    f16 *wqh,*wql,*wkh,*wkl,*wvh,*wvl,*woh,*wol,*w13h,*w13l,*w2h,*w2l,*owh,*owl;
    SYM(wqh, w_qh); SYM(wql, w_ql); SYM(wkh, w_kh); SYM(wkl, w_kl);
    SYM(wvh, w_vh); SYM(wvl, w_vl); SYM(woh, w_oh); SYM(wol, w_ol);
    SYM(w13h, w_13h); SYM(w13l, w_13l);
    SYM(w2h, w_2h); SYM(w2l, w_2l); SYM(owh, w_owh); SYM(owl, w_owl);

    // ---- weight conversions ----
    launch_tsplit(proj_w1, pw1h, pw1l, LAT_, HID_, 1);
    launch_tsplit(proj_w2, pw2h, pw2l, HID_, K_*D_, 1);
    launch_tsplit_f16(wq, wqh, wql, D_, D_, 2);
    launch_tsplit_f16(wk, wkh, wkl, D_, NKV_*HD_, 2);
    launch_tsplit_f16(wv, wvh, wvl, D_, NKV_*HD_, 2);
    launch_tsplit_f16(wo, woh, wol, D_, D_, 2);
    launch_tsplit_f16(w1, w13h, w13l, D_, FFN_, 2, 2, 0);   // even rows
    launch_tsplit_f16(w3, w13h, w13l, D_, FFN_, 2, 2, 1);   // odd rows
    launch_tsplit_f16(w2, w2h, w2l, FFN_, D_, 2);
    launch_tsplit_f16(out_w, owh, owl, D_, V_, 1);
    launch_split(spectra, sph, spl, (size_t)B_*LAT_);

    // ---- spectral projection (bf16 3-term; tiny M) ----
    launch_bgemm(sph, spl, pw1h, pw1l, nullptr, h1h, h1l, nullptr,
                 B_, HID_, LAT_, LAT_, LAT_, HID_, 0,0,0,0,0,0, 1,1,1, 1.f, 0, 0, 0);
    gelu_bias_pair_kernel<<<(B_*HID_ + 255)/256, 256>>>(h1h, h1l, proj_b1, B_*HID_);
    launch_bgemm(h1h, h1l, pw2h, pw2l, spec, nullptr, nullptr, nullptr,
                 B_, K_*D_, HID_, HID_, HID_, K_*D_, 0,0,0,0,0,0, 1,1,1, 1.f, 0, 0, 0);
    bias_add_kernel<<<(B_*K_*D_ + 255)/256, 256>>>(spec, proj_b2, B_*K_*D_, K_*D_);
    layernorm_kernel<<<B_*K_, 256>>>(spec, proj_ln_g, proj_ln_b);

    embed_kernel<<<B_*S_, 256>>>(input_ids, spos, tok_emb, spec, h);

    const float inv_sqrt_hd = 0.08838834764831845f;
    const int M = B_*S_;

    for (int l = 0; l < 2; l++) {
        const f16 *Wqh = wqh + (size_t)l*D_*D_,        *Wql = wql + (size_t)l*D_*D_;
        const f16 *Wkh = wkh + (size_t)l*NKV_*HD_*D_,  *Wkl = wkl + (size_t)l*NKV_*HD_*D_;
        const f16 *Wvh = wvh + (size_t)l*NKV_*HD_*D_,  *Wvl = wvl + (size_t)l*NKV_*HD_*D_;
        const f16 *Woh = woh + (size_t)l*D_*D_,        *Wol = wol + (size_t)l*D_*D_;
        const f16 *W13h = w13h + (size_t)l*2*FFN_*D_,  *W13l = w13l + (size_t)l*2*FFN_*D_;
        const f16 *W2h = w2h + (size_t)l*D_*FFN_,      *W2l = w2l + (size_t)l*D_*FFN_;

        rmsnorm_f16_kernel<<<M, 256>>>(h, attn_norm + (size_t)l*D_, xf);

        launch_fgemm(xf, Wqh, Wql, nullptr, qh, ql, nullptr,
                     M, D_, D_, D_, D_, D_, 1.f, 3, 0);
        launch_fgemm(xf, Wkh, Wkl, nullptr, kh, kl, nullptr,
                     M, NKV_*HD_, D_, D_, D_, NKV_*HD_, 1.f, 3, 0);
        launch_fgemm(xf, Wvh, Wvl, v, nullptr, nullptr, nullptr,
                     M, NKV_*HD_, D_, D_, D_, NKV_*HD_, 1.f, 0, 0);

        launch_tsplit(v, vth, vtl, S_, NKV_*HD_, B_);

        launch_bgemm(qh, ql, kh, kl, sc, nullptr, nullptr, nullptr,
                     S_, S_, HD_, D_, NKV_*HD_, S_,
                     (long long)S_*D_, (long long)HD_,
                     (long long)S_*NKV_*HD_, (long long)HD_,
                     (long long)NH_*S_*S_, (long long)S_*S_,
                     NH_, NREP_, B_*NH_, inv_sqrt_hd, 0, 1, 0);

        softmax_split_kernel<<<B_*NH_*S_, 128>>>(sc, ph, pl);

        launch_bgemm(ph, pl, vth, vtl, nullptr, nullptr, nullptr, atf,
                     S_, HD_, S_, S_, S_, D_,
                     (long long)NH_*S_*S_, (long long)S_*S_,
                     (long long)NKV_*HD_*S_, (long long)HD_*S_,
                     (long long)S_*D_, (long long)HD_,
                     NH_, NREP_, B_*NH_, 1.f, 0, 0, 1);

        launch_fgemm(atf, Woh, Wol, h, nullptr, nullptr, nullptr,
                     M, D_, D_, D_, D_, D_, 1.f, 0, 1);

        rmsnorm_f16_kernel<<<M, 256>>>(h, ffn_norm + (size_t)l*D_, xf);
        // fused W1+W3 swiglu: N = 2*FFN, interleaved gate/value columns -> ff (ldc = FFN)
        launch_fgemm(xf, W13h, W13l, nullptr, nullptr, nullptr, ff,
                     M, 2*FFN_, D_, D_, D_, FFN_, 1.f, 4, 0);
        launch_fgemm(ff, W2h, W2l, h, nullptr, nullptr, nullptr,
                     M, D_, FFN_, FFN_, FFN_, D_, 1.f, 0, 1);
    }

    rmsnorm_f16_kernel<<<M, 256>>>(h, norm_w, xf);
    launch_fgemm(xf, owh, owl, out, nullptr, nullptr, nullptr,
                 M, V_, D_, D_, D_, V_, 1.f, 0, 0);
}